// round 8
// baseline (speedup 1.0000x reference)
#include <cuda_runtime.h>
#include <math_constants.h>

#define B_   8
#define N_   4096
#define F_   64
#define P_   1024
#define K_   16
#define CPF_ 32
#define CF_  96      // CPF + F
#define C_   128
#define DM_  2
#define KK_  256     // K*K
#define EPS_ 0.001f
#define M_   4       // points per block in point_kernel

// Scratch for kNN indices (allocation-free rule: __device__ global)
__device__ int g_idx[B_ * P_ * K_];

// ---------------------------------------------------------------------------
// kNN: warp per query. Warp-distributed sorted top-32 (lane l = rank l).
// FROZEN numerics: dot = k-ordered FMA chain; norms = square+reduce no FMA;
// d2 = (|q|^2 - 2*dot) + |p|^2; lexicographic (d2, index) tie-break.
// Also writes the qrs passthrough (out[0 : B*P*3)).
// ---------------------------------------------------------------------------
__global__ void knn_kernel(const float* __restrict__ pts, float* __restrict__ out) {
    extern __shared__ float4 sp[];   // 4096 x (x, y, z, |p|^2) = 64 KB

    const int batch = blockIdx.x >> 7;      // 128 blocks per batch
    const int warp  = threadIdx.x >> 5;     // 8 warps = 8 queries / block
    const int lane  = threadIdx.x & 31;

    const float* bp = pts + batch * N_ * 3;
    for (int i = threadIdx.x; i < N_; i += blockDim.x) {
        float x = bp[i * 3 + 0], y = bp[i * 3 + 1], z = bp[i * 3 + 2];
        float pn = __fadd_rn(__fadd_rn(__fmul_rn(x, x), __fmul_rn(y, y)), __fmul_rn(z, z));
        sp[i] = make_float4(x, y, z, pn);
    }
    {
        int base = ((blockIdx.x & 127) << 3) * 3;
        if (threadIdx.x < 24)
            out[batch * P_ * 3 + base + threadIdx.x] = bp[base + threadIdx.x];
    }
    __syncthreads();

    const int p = ((blockIdx.x & 127) << 3) + warp;
    const float4 q = sp[p];

    float ld = CUDART_INF_F;
    int   li = 0x7fffffff;
    const unsigned FULL = 0xffffffffu;

    #pragma unroll 1
    for (int r = 0; r < N_ / 32; r++) {
        int n = (r << 5) + lane;
        float4 c = sp[n];
        float dot = __fmaf_rn(q.z, c.z, __fmaf_rn(q.y, c.y, __fmul_rn(q.x, c.x)));
        float d2 = __fadd_rn(__fsub_rn(q.w, __fmul_rn(2.0f, dot)), c.w);

        float wd = __shfl_sync(FULL, ld, 31);
        int   wi = __shfl_sync(FULL, li, 31);
        bool pass = (d2 < wd) || (d2 == wd && n < wi);
        unsigned mask = __ballot_sync(FULL, pass);
        while (mask) {
            int src = __ffs(mask) - 1;
            mask &= mask - 1;
            float dn = __shfl_sync(FULL, d2, src);
            int   in = __shfl_sync(FULL, n, src);
            bool gt = (ld > dn) || (ld == dn && li > in);
            unsigned gb = __ballot_sync(FULL, gt);
            float pd = __shfl_up_sync(FULL, ld, 1);
            int   pi = __shfl_up_sync(FULL, li, 1);
            if (gb) {
                int pos = __ffs(gb) - 1;
                if (lane > pos)      { ld = pd; li = pi; }
                else if (lane == pos){ ld = dn; li = in; }
            }
        }
    }
    if (!(lane & 1))
        g_idx[(batch * P_ + p) * K_ + (lane >> 1)] = li;
}

// ---------------------------------------------------------------------------
// Fused MLP chain, M_=4 points per block, 128 threads.
// Weight loaded once per output element, used for all 4 points (L1 traffic /4).
// ---------------------------------------------------------------------------
__device__ __forceinline__ float elu_f(float x) {
    return x > 0.0f ? x : expm1f(x);
}

struct PSmem {
    int   idx[M_][K_];            // 256 B
    float local[M_][K_ * 3];      // 768 B
    float nnin[M_][K_][CF_];      // 24 KB   cols [0:32)=f, [32:96)=features
    float h0[M_][K_][CPF_];       // 8 KB
    float xa[M_][KK_];            // 4 KB
    float xb[M_][KK_];            // 4 KB
    float fx[M_][K_][CF_];        // 24 KB
    float t[M_][CF_ * DM_];       // 3 KB
};

__global__ __launch_bounds__(128) void point_kernel(
    const float* __restrict__ pts,    const float* __restrict__ features,
    const float* __restrict__ w_fts0, const float* __restrict__ bn_fts0,
    const float* __restrict__ w_fts1, const float* __restrict__ bn_fts1,
    const float* __restrict__ w_x0,   const float* __restrict__ bn_x0,
    const float* __restrict__ w_x1,   const float* __restrict__ bn_x1,
    const float* __restrict__ w_x2,   const float* __restrict__ bn_x2,
    const float* __restrict__ w_dw,   const float* __restrict__ w_pw,
    const float* __restrict__ bn_sep, float* __restrict__ out)
{
    extern __shared__ char smem_raw[];
    PSmem& S = *reinterpret_cast<PSmem*>(smem_raw);

    const int tid = threadIdx.x;
    const int b   = blockIdx.x >> 8;               // 256 blocks per batch
    const int pq0 = (blockIdx.x & 255) * M_;       // first query idx in batch
    const int pg0 = blockIdx.x * M_;               // first global point idx

    if (tid < M_ * K_)
        S.idx[tid >> 4][tid & 15] = g_idx[pg0 * K_ + tid];
    __syncthreads();

    const float* bpts = pts + b * N_ * 3;
    // FIX (R7): grid-stride — M_*48 = 192 > blockDim(128); the R6->R7 'if'
    // version left local[2][32:48] and local[3][*] unwritten (rel_err 0.36).
    for (int e = tid; e < M_ * 48; e += 128) {
        int p = e / 48, r = e - p * 48;
        int k = r / 3, c = r - 3 * k;
        S.local[p][r] = bpts[S.idx[p][k] * 3 + c] - bpts[(pq0 + p) * 3 + c];
    }
    const float* bft = features + b * N_ * F_;
    for (int e = tid; e < M_ * K_ * F_; e += 128) {
        int p = e >> 10, k = (e >> 6) & 15, f = e & 63;
        S.nnin[p][k][CPF_ + f] = bft[S.idx[p][k] * F_ + f];
    }
    __syncthreads();

    // stage A: h0 = bn0(elu(local @ w_fts0))   (M x 16 x 32)
    for (int e = tid; e < K_ * CPF_; e += 128) {
        int k = e >> 5, j = e & 31;
        float w0 = __ldg(w_fts0 + 0 * CPF_ + j);
        float w1 = __ldg(w_fts0 + 1 * CPF_ + j);
        float w2 = __ldg(w_fts0 + 2 * CPF_ + j);
        float g  = __ldg(bn_fts0 + j);
        float bb = __ldg(bn_fts0 + CPF_ + j);
        float mm = __ldg(bn_fts0 + 2 * CPF_ + j);
        float vv = __ldg(bn_fts0 + 3 * CPF_ + j);
        float rs = __fdiv_rn(1.0f, __fsqrt_rn(vv + EPS_));
        #pragma unroll
        for (int p = 0; p < M_; p++) {
            float a = S.local[p][k * 3 + 0] * w0
                    + S.local[p][k * 3 + 1] * w1
                    + S.local[p][k * 3 + 2] * w2;
            S.h0[p][k][j] = (elu_f(a) - mm) * g * rs + bb;
        }
    }
    __syncthreads();

    // stage B: f = bn1(elu(h0 @ w_fts1)) -> nnin[:, :, 0:32]
    for (int e = tid; e < K_ * CPF_; e += 128) {
        int k = e >> 5, j = e & 31;
        float acc[M_] = {0.f, 0.f, 0.f, 0.f};
        #pragma unroll
        for (int j0 = 0; j0 < CPF_; j0++) {
            float w = __ldg(w_fts1 + j0 * CPF_ + j);
            #pragma unroll
            for (int p = 0; p < M_; p++) acc[p] += S.h0[p][k][j0] * w;
        }
        float g  = __ldg(bn_fts1 + j);
        float bb = __ldg(bn_fts1 + CPF_ + j);
        float mm = __ldg(bn_fts1 + 2 * CPF_ + j);
        float vv = __ldg(bn_fts1 + 3 * CPF_ + j);
        float rs = __fdiv_rn(1.0f, __fsqrt_rn(vv + EPS_));
        #pragma unroll
        for (int p = 0; p < M_; p++)
            S.nnin[p][k][j] = (elu_f(acc[p]) - mm) * g * rs + bb;
    }

    // stage C: x0 = bn_x0(elu(local @ w_x0))   (reads local only; barrier after)
    for (int e = tid; e < KK_; e += 128) {
        float acc[M_] = {0.f, 0.f, 0.f, 0.f};
        #pragma unroll
        for (int kc = 0; kc < 48; kc++) {
            float w = __ldg(w_x0 + kc * KK_ + e);
            #pragma unroll
            for (int p = 0; p < M_; p++) acc[p] += S.local[p][kc] * w;
        }
        float g  = __ldg(bn_x0 + e);
        float bb = __ldg(bn_x0 + KK_ + e);
        float mm = __ldg(bn_x0 + 2 * KK_ + e);
        float vv = __ldg(bn_x0 + 3 * KK_ + e);
        float rs = __fdiv_rn(1.0f, __fsqrt_rn(vv + EPS_));
        #pragma unroll
        for (int p = 0; p < M_; p++)
            S.xa[p][e] = (elu_f(acc[p]) - mm) * g * rs + bb;
    }
    __syncthreads();

    // stage D: x1[c][m] = bn_x1(elu(sum_k x0[k][c] * w_x1[k][c][m]))
    for (int e = tid; e < KK_; e += 128) {
        int c = e >> 4, m = e & 15;
        float acc[M_] = {0.f, 0.f, 0.f, 0.f};
        #pragma unroll
        for (int k = 0; k < 16; k++) {
            float w = __ldg(w_x1 + (k * 16 + c) * 16 + m);
            #pragma unroll
            for (int p = 0; p < M_; p++) acc[p] += S.xa[p][k * 16 + c] * w;
        }
        float g  = __ldg(bn_x1 + e);
        float bb = __ldg(bn_x1 + KK_ + e);
        float mm = __ldg(bn_x1 + 2 * KK_ + e);
        float vv = __ldg(bn_x1 + 3 * KK_ + e);
        float rs = __fdiv_rn(1.0f, __fsqrt_rn(vv + EPS_));
        #pragma unroll
        for (int p = 0; p < M_; p++)
            S.xb[p][e] = (elu_f(acc[p]) - mm) * g * rs + bb;
    }
    __syncthreads();

    // stage E: x2[c][m] = bn_x2(sum_k x1[k][c] * w_x2[k][c][m])  (no elu)
    for (int e = tid; e < KK_; e += 128) {
        int c = e >> 4, m = e & 15;
        float acc[M_] = {0.f, 0.f, 0.f, 0.f};
        #pragma unroll
        for (int k = 0; k < 16; k++) {
            float w = __ldg(w_x2 + (k * 16 + c) * 16 + m);
            #pragma unroll
            for (int p = 0; p < M_; p++) acc[p] += S.xb[p][k * 16 + c] * w;
        }
        float g  = __ldg(bn_x2 + e);
        float bb = __ldg(bn_x2 + KK_ + e);
        float mm = __ldg(bn_x2 + 2 * KK_ + e);
        float vv = __ldg(bn_x2 + 3 * KK_ + e);
        float rs = __fdiv_rn(1.0f, __fsqrt_rn(vv + EPS_));
        #pragma unroll
        for (int p = 0; p < M_; p++)
            S.xa[p][e] = (acc[p] - mm) * g * rs + bb;
    }
    __syncthreads();

    // stage F: fts_X[i][f] = sum_j x2[i][j] * nnin[j][f]   (M x 16 x 96, smem-only)
    for (int e = tid; e < M_ * K_ * CF_; e += 128) {
        int p = e / (K_ * CF_), r = e - p * (K_ * CF_);
        int i = r / CF_, f = r - i * CF_;
        float a = 0.0f;
        #pragma unroll
        for (int j = 0; j < 16; j++)
            a += S.xa[p][i * 16 + j] * S.nnin[p][j][f];
        S.fx[p][i][f] = a;
    }
    __syncthreads();

    // stage G: t[c][m] = sum_k fts_X[k][c] * w_dw[k][c][m]   (96 x 2)
    for (int e = tid; e < CF_ * DM_; e += 128) {
        int c = e >> 1, m = e & 1;
        float acc[M_] = {0.f, 0.f, 0.f, 0.f};
        #pragma unroll
        for (int k = 0; k < 16; k++) {
            float w = __ldg(w_dw + (k * CF_ + c) * DM_ + m);
            #pragma unroll
            for (int p = 0; p < M_; p++) acc[p] += S.fx[p][k][c] * w;
        }
        #pragma unroll
        for (int p = 0; p < M_; p++) S.t[p][e] = acc[p];
    }
    __syncthreads();

    // stage H: out[o] = bn_sep(elu(sum_i t[i] * w_pw[i][o]))   (128 outputs)
    {
        int o = tid;
        float acc[M_] = {0.f, 0.f, 0.f, 0.f};
        #pragma unroll 4
        for (int i = 0; i < CF_ * DM_; i++) {
            float w = __ldg(w_pw + i * C_ + o);
            #pragma unroll
            for (int p = 0; p < M_; p++) acc[p] += S.t[p][i] * w;
        }
        float g  = __ldg(bn_sep + o);
        float bb = __ldg(bn_sep + C_ + o);
        float mm = __ldg(bn_sep + 2 * C_ + o);
        float vv = __ldg(bn_sep + 3 * C_ + o);
        float rs = __fdiv_rn(1.0f, __fsqrt_rn(vv + EPS_));
        #pragma unroll
        for (int p = 0; p < M_; p++)
            out[B_ * P_ * 3 + (pg0 + p) * C_ + o] = (elu_f(acc[p]) - mm) * g * rs + bb;
    }
}

// ---------------------------------------------------------------------------
extern "C" void kernel_launch(void* const* d_in, const int* in_sizes, int n_in,
                              void* d_out, int out_size) {
    const float* pts      = (const float*)d_in[0];
    const float* features = (const float*)d_in[1];
    const float* w_fts0   = (const float*)d_in[2];
    const float* bn_fts0  = (const float*)d_in[3];
    const float* w_fts1   = (const float*)d_in[4];
    const float* bn_fts1  = (const float*)d_in[5];
    const float* w_x0     = (const float*)d_in[6];
    const float* bn_x0    = (const float*)d_in[7];
    const float* w_x1     = (const float*)d_in[8];
    const float* bn_x1    = (const float*)d_in[9];
    const float* w_x2     = (const float*)d_in[10];
    const float* bn_x2    = (const float*)d_in[11];
    const float* w_dw     = (const float*)d_in[12];
    const float* w_pw     = (const float*)d_in[13];
    const float* bn_sep   = (const float*)d_in[14];
    float* out = (float*)d_out;

    cudaFuncSetAttribute(knn_kernel, cudaFuncAttributeMaxDynamicSharedMemorySize, 65536);
    knn_kernel<<<B_ * 128, 256, 65536>>>(pts, out);

    cudaFuncSetAttribute(point_kernel, cudaFuncAttributeMaxDynamicSharedMemorySize,
                         (int)sizeof(PSmem));
    point_kernel<<<B_ * P_ / M_, 128, sizeof(PSmem)>>>(pts, features,
                                   w_fts0, bn_fts0, w_fts1, bn_fts1,
                                   w_x0, bn_x0, w_x1, bn_x1, w_x2, bn_x2,
                                   w_dw, w_pw, bn_sep, out);
}

// round 9
// speedup vs baseline: 1.4513x; 1.4513x over previous
#include <cuda_runtime.h>
#include <math_constants.h>

#define B_   8
#define N_   4096
#define F_   64
#define P_   1024
#define K_   16
#define CPF_ 32
#define CF_  96      // CPF + F
#define C_   128
#define DM_  2
#define KK_  256     // K*K
#define EPS_ 0.001f
#define M_   4       // points per block in point_kernel
#define PT_  256     // point_kernel threads

// Scratch for kNN indices (allocation-free rule: __device__ global)
__device__ int g_idx[B_ * P_ * K_];

// ---------------------------------------------------------------------------
// kNN: warp per query. Warp-distributed sorted top-32 (lane l = rank l).
// FROZEN numerics: dot = k-ordered FMA chain; norms = square+reduce no FMA;
// d2 = (|q|^2 - 2*dot) + |p|^2; lexicographic (d2, index) tie-break.
// Also writes the qrs passthrough (out[0 : B*P*3)).
// ---------------------------------------------------------------------------
__global__ void knn_kernel(const float* __restrict__ pts, float* __restrict__ out) {
    extern __shared__ float4 sp[];   // 4096 x (x, y, z, |p|^2) = 64 KB

    const int batch = blockIdx.x >> 7;      // 128 blocks per batch
    const int warp  = threadIdx.x >> 5;     // 8 warps = 8 queries / block
    const int lane  = threadIdx.x & 31;

    const float* bp = pts + batch * N_ * 3;
    for (int i = threadIdx.x; i < N_; i += blockDim.x) {
        float x = bp[i * 3 + 0], y = bp[i * 3 + 1], z = bp[i * 3 + 2];
        float pn = __fadd_rn(__fadd_rn(__fmul_rn(x, x), __fmul_rn(y, y)), __fmul_rn(z, z));
        sp[i] = make_float4(x, y, z, pn);
    }
    {
        int base = ((blockIdx.x & 127) << 3) * 3;
        if (threadIdx.x < 24)
            out[batch * P_ * 3 + base + threadIdx.x] = bp[base + threadIdx.x];
    }
    __syncthreads();

    const int p = ((blockIdx.x & 127) << 3) + warp;
    const float4 q = sp[p];

    float ld = CUDART_INF_F;
    int   li = 0x7fffffff;
    const unsigned FULL = 0xffffffffu;

    #pragma unroll 1
    for (int r = 0; r < N_ / 32; r++) {
        int n = (r << 5) + lane;
        float4 c = sp[n];
        float dot = __fmaf_rn(q.z, c.z, __fmaf_rn(q.y, c.y, __fmul_rn(q.x, c.x)));
        float d2 = __fadd_rn(__fsub_rn(q.w, __fmul_rn(2.0f, dot)), c.w);

        float wd = __shfl_sync(FULL, ld, 31);
        int   wi = __shfl_sync(FULL, li, 31);
        bool pass = (d2 < wd) || (d2 == wd && n < wi);
        unsigned mask = __ballot_sync(FULL, pass);
        while (mask) {
            int src = __ffs(mask) - 1;
            mask &= mask - 1;
            float dn = __shfl_sync(FULL, d2, src);
            int   in = __shfl_sync(FULL, n, src);
            bool gt = (ld > dn) || (ld == dn && li > in);
            unsigned gb = __ballot_sync(FULL, gt);
            float pd = __shfl_up_sync(FULL, ld, 1);
            int   pi = __shfl_up_sync(FULL, li, 1);
            if (gb) {
                int pos = __ffs(gb) - 1;
                if (lane > pos)      { ld = pd; li = pi; }
                else if (lane == pos){ ld = dn; li = in; }
            }
        }
    }
    if (!(lane & 1))
        g_idx[(batch * P_ + p) * K_ + (lane >> 1)] = li;
}

// ---------------------------------------------------------------------------
// Fused MLP chain, M_=4 points per block, 256 threads.
// Weight loaded once per output element, used for all 4 points (L1 traffic /4).
// F+G fused (no fx buffer) -> 44KB smem -> 5 blocks/SM, 40 warps.
// ---------------------------------------------------------------------------
__device__ __forceinline__ float elu_f(float x) {
    return x > 0.0f ? x : expm1f(x);
}

struct PSmem {
    int   idx[M_][K_];            // 256 B
    float local[M_][K_ * 3];      // 768 B
    float nnin[M_][K_][CF_];      // 24 KB   cols [0:32)=f, [32:96)=features
    float h0[M_][K_][CPF_];       // 8 KB
    float xa[M_][KK_];            // 4 KB
    float xb[M_][KK_];            // 4 KB
    float t[M_][CF_ * DM_];       // 3 KB
};                                // ~44.3 KB

__global__ __launch_bounds__(PT_) void point_kernel(
    const float* __restrict__ pts,    const float* __restrict__ features,
    const float* __restrict__ w_fts0, const float* __restrict__ bn_fts0,
    const float* __restrict__ w_fts1, const float* __restrict__ bn_fts1,
    const float* __restrict__ w_x0,   const float* __restrict__ bn_x0,
    const float* __restrict__ w_x1,   const float* __restrict__ bn_x1,
    const float* __restrict__ w_x2,   const float* __restrict__ bn_x2,
    const float* __restrict__ w_dw,   const float* __restrict__ w_pw,
    const float* __restrict__ bn_sep, float* __restrict__ out)
{
    extern __shared__ char smem_raw[];
    PSmem& S = *reinterpret_cast<PSmem*>(smem_raw);

    const int tid = threadIdx.x;
    const int b   = blockIdx.x >> 8;               // 256 blocks per batch
    const int pq0 = (blockIdx.x & 255) * M_;       // first query idx in batch
    const int pg0 = blockIdx.x * M_;               // first global point idx

    if (tid < M_ * K_)
        S.idx[tid >> 4][tid & 15] = g_idx[pg0 * K_ + tid];
    __syncthreads();

    const float* bpts = pts + b * N_ * 3;
    if (tid < M_ * 48) {                     // 192 <= 256 threads: single pass
        int p = tid / 48, r = tid - p * 48;
        int k = r / 3, c = r - 3 * k;
        S.local[p][r] = bpts[S.idx[p][k] * 3 + c] - bpts[(pq0 + p) * 3 + c];
    }
    // features: float4 loads (F_=64 -> 16 float4 per neighbor row)
    const float4* bft4 = (const float4*)(features + b * N_ * F_);
    for (int e = tid; e < M_ * K_ * (F_ / 4); e += PT_) {
        int p = e >> 8, k = (e >> 4) & 15, f4 = e & 15;
        float4 v = __ldg(bft4 + S.idx[p][k] * (F_ / 4) + f4);
        *(float4*)&S.nnin[p][k][CPF_ + f4 * 4] = v;
    }
    __syncthreads();

    // stage A: h0 = bn0(elu(local @ w_fts0))   (M x 16 x 32)
    for (int e = tid; e < K_ * CPF_; e += PT_) {
        int k = e >> 5, j = e & 31;
        float w0 = __ldg(w_fts0 + 0 * CPF_ + j);
        float w1 = __ldg(w_fts0 + 1 * CPF_ + j);
        float w2 = __ldg(w_fts0 + 2 * CPF_ + j);
        float g  = __ldg(bn_fts0 + j);
        float bb = __ldg(bn_fts0 + CPF_ + j);
        float mm = __ldg(bn_fts0 + 2 * CPF_ + j);
        float vv = __ldg(bn_fts0 + 3 * CPF_ + j);
        float rs = __fdiv_rn(1.0f, __fsqrt_rn(vv + EPS_));
        #pragma unroll
        for (int p = 0; p < M_; p++) {
            float a = S.local[p][k * 3 + 0] * w0
                    + S.local[p][k * 3 + 1] * w1
                    + S.local[p][k * 3 + 2] * w2;
            S.h0[p][k][j] = (elu_f(a) - mm) * g * rs + bb;
        }
    }
    __syncthreads();

    // stage B: f = bn1(elu(h0 @ w_fts1)) -> nnin[:, :, 0:32]
    for (int e = tid; e < K_ * CPF_; e += PT_) {
        int k = e >> 5, j = e & 31;
        float acc[M_] = {0.f, 0.f, 0.f, 0.f};
        #pragma unroll
        for (int j0 = 0; j0 < CPF_; j0++) {
            float w = __ldg(w_fts1 + j0 * CPF_ + j);
            #pragma unroll
            for (int p = 0; p < M_; p++) acc[p] += S.h0[p][k][j0] * w;
        }
        float g  = __ldg(bn_fts1 + j);
        float bb = __ldg(bn_fts1 + CPF_ + j);
        float mm = __ldg(bn_fts1 + 2 * CPF_ + j);
        float vv = __ldg(bn_fts1 + 3 * CPF_ + j);
        float rs = __fdiv_rn(1.0f, __fsqrt_rn(vv + EPS_));
        #pragma unroll
        for (int p = 0; p < M_; p++)
            S.nnin[p][k][j] = (elu_f(acc[p]) - mm) * g * rs + bb;
    }

    // stage C: x0 = bn_x0(elu(local @ w_x0))   (reads local only; barrier after)
    for (int e = tid; e < KK_; e += PT_) {
        float acc[M_] = {0.f, 0.f, 0.f, 0.f};
        #pragma unroll
        for (int kc = 0; kc < 48; kc++) {
            float w = __ldg(w_x0 + kc * KK_ + e);
            #pragma unroll
            for (int p = 0; p < M_; p++) acc[p] += S.local[p][kc] * w;
        }
        float g  = __ldg(bn_x0 + e);
        float bb = __ldg(bn_x0 + KK_ + e);
        float mm = __ldg(bn_x0 + 2 * KK_ + e);
        float vv = __ldg(bn_x0 + 3 * KK_ + e);
        float rs = __fdiv_rn(1.0f, __fsqrt_rn(vv + EPS_));
        #pragma unroll
        for (int p = 0; p < M_; p++)
            S.xa[p][e] = (elu_f(acc[p]) - mm) * g * rs + bb;
    }
    __syncthreads();

    // stage D: x1[c][m] = bn_x1(elu(sum_k x0[k][c] * w_x1[k][c][m]))
    for (int e = tid; e < KK_; e += PT_) {
        int c = e >> 4, m = e & 15;
        float acc[M_] = {0.f, 0.f, 0.f, 0.f};
        #pragma unroll
        for (int k = 0; k < 16; k++) {
            float w = __ldg(w_x1 + (k * 16 + c) * 16 + m);
            #pragma unroll
            for (int p = 0; p < M_; p++) acc[p] += S.xa[p][k * 16 + c] * w;
        }
        float g  = __ldg(bn_x1 + e);
        float bb = __ldg(bn_x1 + KK_ + e);
        float mm = __ldg(bn_x1 + 2 * KK_ + e);
        float vv = __ldg(bn_x1 + 3 * KK_ + e);
        float rs = __fdiv_rn(1.0f, __fsqrt_rn(vv + EPS_));
        #pragma unroll
        for (int p = 0; p < M_; p++)
            S.xb[p][e] = (elu_f(acc[p]) - mm) * g * rs + bb;
    }
    __syncthreads();

    // stage E: x2[c][m] = bn_x2(sum_k x1[k][c] * w_x2[k][c][m])  (no elu)
    for (int e = tid; e < KK_; e += PT_) {
        int c = e >> 4, m = e & 15;
        float acc[M_] = {0.f, 0.f, 0.f, 0.f};
        #pragma unroll
        for (int k = 0; k < 16; k++) {
            float w = __ldg(w_x2 + (k * 16 + c) * 16 + m);
            #pragma unroll
            for (int p = 0; p < M_; p++) acc[p] += S.xb[p][k * 16 + c] * w;
        }
        float g  = __ldg(bn_x2 + e);
        float bb = __ldg(bn_x2 + KK_ + e);
        float mm = __ldg(bn_x2 + 2 * KK_ + e);
        float vv = __ldg(bn_x2 + 3 * KK_ + e);
        float rs = __fdiv_rn(1.0f, __fsqrt_rn(vv + EPS_));
        #pragma unroll
        for (int p = 0; p < M_; p++)
            S.xa[p][e] = (acc[p] - mm) * g * rs + bb;
    }
    __syncthreads();

    // stage F+G fused: t[c][m] = sum_k (sum_j x2[k][j] * nnin[j][c]) * w_dw[k][c][m]
    // (j ascending inside k ascending: same per-output order as separate F,G)
    for (int e = tid; e < M_ * CF_ * DM_; e += PT_) {
        int p = e / (CF_ * DM_), r = e - p * (CF_ * DM_);
        int c = r >> 1, m = r & 1;
        float acc = 0.0f;
        #pragma unroll
        for (int k = 0; k < 16; k++) {
            float fx = 0.0f;
            #pragma unroll
            for (int j = 0; j < 16; j++)
                fx += S.xa[p][k * 16 + j] * S.nnin[p][j][c];
            acc += fx * __ldg(w_dw + (k * CF_ + c) * DM_ + m);
        }
        S.t[p][r] = acc;
    }
    __syncthreads();

    // stage H: out[o] = bn_sep(elu(sum_i t[i] * w_pw[i][o]))   (128 outputs)
    if (tid < C_) {
        int o = tid;
        float acc[M_] = {0.f, 0.f, 0.f, 0.f};
        #pragma unroll 4
        for (int i = 0; i < CF_ * DM_; i++) {
            float w = __ldg(w_pw + i * C_ + o);
            #pragma unroll
            for (int p = 0; p < M_; p++) acc[p] += S.t[p][i] * w;
        }
        float g  = __ldg(bn_sep + o);
        float bb = __ldg(bn_sep + C_ + o);
        float mm = __ldg(bn_sep + 2 * C_ + o);
        float vv = __ldg(bn_sep + 3 * C_ + o);
        float rs = __fdiv_rn(1.0f, __fsqrt_rn(vv + EPS_));
        #pragma unroll
        for (int p = 0; p < M_; p++)
            out[B_ * P_ * 3 + (pg0 + p) * C_ + o] = (elu_f(acc[p]) - mm) * g * rs + bb;
    }
}

// ---------------------------------------------------------------------------
extern "C" void kernel_launch(void* const* d_in, const int* in_sizes, int n_in,
                              void* d_out, int out_size) {
    const float* pts      = (const float*)d_in[0];
    const float* features = (const float*)d_in[1];
    const float* w_fts0   = (const float*)d_in[2];
    const float* bn_fts0  = (const float*)d_in[3];
    const float* w_fts1   = (const float*)d_in[4];
    const float* bn_fts1  = (const float*)d_in[5];
    const float* w_x0     = (const float*)d_in[6];
    const float* bn_x0    = (const float*)d_in[7];
    const float* w_x1     = (const float*)d_in[8];
    const float* bn_x1    = (const float*)d_in[9];
    const float* w_x2     = (const float*)d_in[10];
    const float* bn_x2    = (const float*)d_in[11];
    const float* w_dw     = (const float*)d_in[12];
    const float* w_pw     = (const float*)d_in[13];
    const float* bn_sep   = (const float*)d_in[14];
    float* out = (float*)d_out;

    cudaFuncSetAttribute(knn_kernel, cudaFuncAttributeMaxDynamicSharedMemorySize, 65536);
    knn_kernel<<<B_ * 128, 256, 65536>>>(pts, out);

    cudaFuncSetAttribute(point_kernel, cudaFuncAttributeMaxDynamicSharedMemorySize,
                         (int)sizeof(PSmem));
    point_kernel<<<B_ * P_ / M_, PT_, sizeof(PSmem)>>>(pts, features,
                                   w_fts0, bn_fts0, w_fts1, bn_fts1,
                                   w_x0, bn_x0, w_x1, bn_x1, w_x2, bn_x2,
                                   w_dw, w_pw, bn_sep, out);
}

// round 10
// speedup vs baseline: 1.5439x; 1.0638x over previous
#include <cuda_runtime.h>
#include <math_constants.h>

#define B_   8
#define N_   4096
#define F_   64
#define P_   1024
#define K_   16
#define CPF_ 32
#define CF_  96      // CPF + F
#define C_   128
#define DM_  2
#define KK_  256     // K*K
#define EPS_ 0.001f
#define M_   4       // points per block in point_kernel
#define PT_  256     // point_kernel threads

// Scratch for kNN indices (allocation-free rule: __device__ global)
__device__ int g_idx[B_ * P_ * K_];

// ---------------------------------------------------------------------------
// kNN: warp per query. Warp-distributed sorted top-32 (lane l = rank l).
// FROZEN numerics: dot = k-ordered FMA chain; norms = square+reduce no FMA;
// d2 = (|q|^2 - 2*dot) + |p|^2; lexicographic (d2, index) tie-break.
// R10: rank-31 threshold kept in broadcast regs, refreshed only after inserts.
// Also writes the qrs passthrough (out[0 : B*P*3)).
// ---------------------------------------------------------------------------
__global__ void knn_kernel(const float* __restrict__ pts, float* __restrict__ out) {
    extern __shared__ float4 sp[];   // 4096 x (x, y, z, |p|^2) = 64 KB

    const int batch = blockIdx.x >> 7;      // 128 blocks per batch
    const int warp  = threadIdx.x >> 5;     // 8 warps = 8 queries / block
    const int lane  = threadIdx.x & 31;

    const float* bp = pts + batch * N_ * 3;
    for (int i = threadIdx.x; i < N_; i += blockDim.x) {
        float x = bp[i * 3 + 0], y = bp[i * 3 + 1], z = bp[i * 3 + 2];
        float pn = __fadd_rn(__fadd_rn(__fmul_rn(x, x), __fmul_rn(y, y)), __fmul_rn(z, z));
        sp[i] = make_float4(x, y, z, pn);
    }
    {
        int base = ((blockIdx.x & 127) << 3) * 3;
        if (threadIdx.x < 24)
            out[batch * P_ * 3 + base + threadIdx.x] = bp[base + threadIdx.x];
    }
    __syncthreads();

    const int p = ((blockIdx.x & 127) << 3) + warp;
    const float4 q = sp[p];

    float ld = CUDART_INF_F;     // this lane's list element (rank = lane)
    int   li = 0x7fffffff;
    float thr_d = CUDART_INF_F;  // broadcast copy of rank-31 entry
    int   thr_i = 0x7fffffff;
    const unsigned FULL = 0xffffffffu;

    #pragma unroll 1
    for (int r = 0; r < N_ / 32; r++) {
        int n = (r << 5) + lane;
        float4 c = sp[n];
        float dot = __fmaf_rn(q.z, c.z, __fmaf_rn(q.y, c.y, __fmul_rn(q.x, c.x)));
        float d2 = __fadd_rn(__fsub_rn(q.w, __fmul_rn(2.0f, dot)), c.w);

        bool pass = (d2 < thr_d) || (d2 == thr_d && n < thr_i);
        unsigned mask = __ballot_sync(FULL, pass);
        if (mask) {
            do {
                int src = __ffs(mask) - 1;
                mask &= mask - 1;
                float dn = __shfl_sync(FULL, d2, src);
                int   in = __shfl_sync(FULL, n, src);
                bool gt = (ld > dn) || (ld == dn && li > in);
                unsigned gb = __ballot_sync(FULL, gt);
                float pd = __shfl_up_sync(FULL, ld, 1);
                int   pi = __shfl_up_sync(FULL, li, 1);
                if (gb) {                       // else: worse than all 32, drop
                    int pos = __ffs(gb) - 1;
                    if (lane > pos)      { ld = pd; li = pi; }
                    else if (lane == pos){ ld = dn; li = in; }
                }
            } while (mask);
            thr_d = __shfl_sync(FULL, ld, 31);
            thr_i = __shfl_sync(FULL, li, 31);
        }
    }
    // dilation D=2: keep even ranks 0,2,...,30
    if (!(lane & 1))
        g_idx[(batch * P_ + p) * K_ + (lane >> 1)] = li;
}

// ---------------------------------------------------------------------------
// Fused MLP chain, M_=4 points per block, 256 threads, 5 blocks/SM.
// Weights loaded once per output element, reused across 4 points.
// Stage F+G: per-(p,c) thread, nnin column cached in regs (LDS traffic /3.8).
// ---------------------------------------------------------------------------
__device__ __forceinline__ float elu_f(float x) {
    return x > 0.0f ? x : expm1f(x);
}

struct PSmem {
    int   idx[M_][K_];            // 256 B
    float local[M_][K_ * 3];      // 768 B
    float nnin[M_][K_][CF_];      // 24 KB   cols [0:32)=f, [32:96)=features
    float h0[M_][K_][CPF_];       // 8 KB
    float xa[M_][KK_];            // 4 KB
    float xb[M_][KK_];            // 4 KB
    float t[M_][CF_ * DM_];       // 3 KB
};                                // ~44.3 KB -> 5 blocks/SM

__global__ __launch_bounds__(PT_, 5) void point_kernel(
    const float* __restrict__ pts,    const float* __restrict__ features,
    const float* __restrict__ w_fts0, const float* __restrict__ bn_fts0,
    const float* __restrict__ w_fts1, const float* __restrict__ bn_fts1,
    const float* __restrict__ w_x0,   const float* __restrict__ bn_x0,
    const float* __restrict__ w_x1,   const float* __restrict__ bn_x1,
    const float* __restrict__ w_x2,   const float* __restrict__ bn_x2,
    const float* __restrict__ w_dw,   const float* __restrict__ w_pw,
    const float* __restrict__ bn_sep, float* __restrict__ out)
{
    extern __shared__ char smem_raw[];
    PSmem& S = *reinterpret_cast<PSmem*>(smem_raw);

    const int tid = threadIdx.x;
    const int b   = blockIdx.x >> 8;               // 256 blocks per batch
    const int pq0 = (blockIdx.x & 255) * M_;       // first query idx in batch
    const int pg0 = blockIdx.x * M_;               // first global point idx

    if (tid < M_ * K_)
        S.idx[tid >> 4][tid & 15] = g_idx[pg0 * K_ + tid];
    __syncthreads();

    const float* bpts = pts + b * N_ * 3;
    if (tid < M_ * 48) {                     // 192 <= 256 threads: single pass
        int p = tid / 48, r = tid - p * 48;
        int k = r / 3, c = r - 3 * k;
        S.local[p][r] = bpts[S.idx[p][k] * 3 + c] - bpts[(pq0 + p) * 3 + c];
    }
    // features: float4 loads (F_=64 -> 16 float4 per neighbor row)
    const float4* bft4 = (const float4*)(features + b * N_ * F_);
    for (int e = tid; e < M_ * K_ * (F_ / 4); e += PT_) {
        int p = e >> 8, k = (e >> 4) & 15, f4 = e & 15;
        float4 v = __ldg(bft4 + S.idx[p][k] * (F_ / 4) + f4);
        *(float4*)&S.nnin[p][k][CPF_ + f4 * 4] = v;
    }
    __syncthreads();

    // stage A: h0 = bn0(elu(local @ w_fts0))   (M x 16 x 32)
    for (int e = tid; e < K_ * CPF_; e += PT_) {
        int k = e >> 5, j = e & 31;
        float w0 = __ldg(w_fts0 + 0 * CPF_ + j);
        float w1 = __ldg(w_fts0 + 1 * CPF_ + j);
        float w2 = __ldg(w_fts0 + 2 * CPF_ + j);
        float g  = __ldg(bn_fts0 + j);
        float bb = __ldg(bn_fts0 + CPF_ + j);
        float mm = __ldg(bn_fts0 + 2 * CPF_ + j);
        float vv = __ldg(bn_fts0 + 3 * CPF_ + j);
        float rs = __fdiv_rn(1.0f, __fsqrt_rn(vv + EPS_));
        #pragma unroll
        for (int p = 0; p < M_; p++) {
            float a = S.local[p][k * 3 + 0] * w0
                    + S.local[p][k * 3 + 1] * w1
                    + S.local[p][k * 3 + 2] * w2;
            S.h0[p][k][j] = (elu_f(a) - mm) * g * rs + bb;
        }
    }
    __syncthreads();

    // stage B: f = bn1(elu(h0 @ w_fts1)) -> nnin[:, :, 0:32]
    for (int e = tid; e < K_ * CPF_; e += PT_) {
        int k = e >> 5, j = e & 31;
        float acc[M_] = {0.f, 0.f, 0.f, 0.f};
        #pragma unroll
        for (int j0 = 0; j0 < CPF_; j0++) {
            float w = __ldg(w_fts1 + j0 * CPF_ + j);
            #pragma unroll
            for (int p = 0; p < M_; p++) acc[p] += S.h0[p][k][j0] * w;
        }
        float g  = __ldg(bn_fts1 + j);
        float bb = __ldg(bn_fts1 + CPF_ + j);
        float mm = __ldg(bn_fts1 + 2 * CPF_ + j);
        float vv = __ldg(bn_fts1 + 3 * CPF_ + j);
        float rs = __fdiv_rn(1.0f, __fsqrt_rn(vv + EPS_));
        #pragma unroll
        for (int p = 0; p < M_; p++)
            S.nnin[p][k][j] = (elu_f(acc[p]) - mm) * g * rs + bb;
    }

    // stage C: x0 = bn_x0(elu(local @ w_x0))   (reads local only; barrier after)
    for (int e = tid; e < KK_; e += PT_) {
        float acc[M_] = {0.f, 0.f, 0.f, 0.f};
        #pragma unroll
        for (int kc = 0; kc < 48; kc++) {
            float w = __ldg(w_x0 + kc * KK_ + e);
            #pragma unroll
            for (int p = 0; p < M_; p++) acc[p] += S.local[p][kc] * w;
        }
        float g  = __ldg(bn_x0 + e);
        float bb = __ldg(bn_x0 + KK_ + e);
        float mm = __ldg(bn_x0 + 2 * KK_ + e);
        float vv = __ldg(bn_x0 + 3 * KK_ + e);
        float rs = __fdiv_rn(1.0f, __fsqrt_rn(vv + EPS_));
        #pragma unroll
        for (int p = 0; p < M_; p++)
            S.xa[p][e] = (elu_f(acc[p]) - mm) * g * rs + bb;
    }
    __syncthreads();

    // stage D: x1[c][m] = bn_x1(elu(sum_k x0[k][c] * w_x1[k][c][m]))
    for (int e = tid; e < KK_; e += PT_) {
        int c = e >> 4, m = e & 15;
        float acc[M_] = {0.f, 0.f, 0.f, 0.f};
        #pragma unroll
        for (int k = 0; k < 16; k++) {
            float w = __ldg(w_x1 + (k * 16 + c) * 16 + m);
            #pragma unroll
            for (int p = 0; p < M_; p++) acc[p] += S.xa[p][k * 16 + c] * w;
        }
        float g  = __ldg(bn_x1 + e);
        float bb = __ldg(bn_x1 + KK_ + e);
        float mm = __ldg(bn_x1 + 2 * KK_ + e);
        float vv = __ldg(bn_x1 + 3 * KK_ + e);
        float rs = __fdiv_rn(1.0f, __fsqrt_rn(vv + EPS_));
        #pragma unroll
        for (int p = 0; p < M_; p++)
            S.xb[p][e] = (elu_f(acc[p]) - mm) * g * rs + bb;
    }
    __syncthreads();

    // stage E: x2[c][m] = bn_x2(sum_k x1[k][c] * w_x2[k][c][m])  (no elu)
    for (int e = tid; e < KK_; e += PT_) {
        int c = e >> 4, m = e & 15;
        float acc[M_] = {0.f, 0.f, 0.f, 0.f};
        #pragma unroll
        for (int k = 0; k < 16; k++) {
            float w = __ldg(w_x2 + (k * 16 + c) * 16 + m);
            #pragma unroll
            for (int p = 0; p < M_; p++) acc[p] += S.xb[p][k * 16 + c] * w;
        }
        float g  = __ldg(bn_x2 + e);
        float bb = __ldg(bn_x2 + KK_ + e);
        float mm = __ldg(bn_x2 + 2 * KK_ + e);
        float vv = __ldg(bn_x2 + 3 * KK_ + e);
        float rs = __fdiv_rn(1.0f, __fsqrt_rn(vv + EPS_));
        #pragma unroll
        for (int p = 0; p < M_; p++)
            S.xa[p][e] = (acc[p] - mm) * g * rs + bb;
    }
    __syncthreads();

    // stage F+G, per-(p,c) thread: nnin column cached in regs, fx computed once,
    // both m outputs accumulated from registers. Same per-output order as
    // separate F,G (j ascending inside k ascending) -> numerics unchanged.
    for (int e = tid; e < M_ * CF_; e += PT_) {
        int p = e / CF_, c = e - p * CF_;
        float nnj[K_];
        #pragma unroll
        for (int j = 0; j < K_; j++) nnj[j] = S.nnin[p][j][c];
        float t0 = 0.0f, t1 = 0.0f;
        #pragma unroll
        for (int k = 0; k < K_; k++) {
            float fx = 0.0f;
            #pragma unroll
            for (int j = 0; j < K_; j++)
                fx += S.xa[p][k * 16 + j] * nnj[j];
            float2 wd = __ldg((const float2*)w_dw + k * CF_ + c);
            t0 += fx * wd.x;
            t1 += fx * wd.y;
        }
        S.t[p][c * DM_ + 0] = t0;
        S.t[p][c * DM_ + 1] = t1;
    }
    __syncthreads();

    // stage H: out[o] = bn_sep(elu(sum_i t[i] * w_pw[i][o]))   (128 outputs)
    if (tid < C_) {
        int o = tid;
        float acc[M_] = {0.f, 0.f, 0.f, 0.f};
        #pragma unroll 4
        for (int i = 0; i < CF_ * DM_; i++) {
            float w = __ldg(w_pw + i * C_ + o);
            #pragma unroll
            for (int p = 0; p < M_; p++) acc[p] += S.t[p][i] * w;
        }
        float g  = __ldg(bn_sep + o);
        float bb = __ldg(bn_sep + C_ + o);
        float mm = __ldg(bn_sep + 2 * C_ + o);
        float vv = __ldg(bn_sep + 3 * C_ + o);
        float rs = __fdiv_rn(1.0f, __fsqrt_rn(vv + EPS_));
        #pragma unroll
        for (int p = 0; p < M_; p++)
            out[B_ * P_ * 3 + (pg0 + p) * C_ + o] = (elu_f(acc[p]) - mm) * g * rs + bb;
    }
}

// ---------------------------------------------------------------------------
extern "C" void kernel_launch(void* const* d_in, const int* in_sizes, int n_in,
                              void* d_out, int out_size) {
    const float* pts      = (const float*)d_in[0];
    const float* features = (const float*)d_in[1];
    const float* w_fts0   = (const float*)d_in[2];
    const float* bn_fts0  = (const float*)d_in[3];
    const float* w_fts1   = (const float*)d_in[4];
    const float* bn_fts1  = (const float*)d_in[5];
    const float* w_x0     = (const float*)d_in[6];
    const float* bn_x0    = (const float*)d_in[7];
    const float* w_x1     = (const float*)d_in[8];
    const float* bn_x1    = (const float*)d_in[9];
    const float* w_x2     = (const float*)d_in[10];
    const float* bn_x2    = (const float*)d_in[11];
    const float* w_dw     = (const float*)d_in[12];
    const float* w_pw     = (const float*)d_in[13];
    const float* bn_sep   = (const float*)d_in[14];
    float* out = (float*)d_out;

    cudaFuncSetAttribute(knn_kernel, cudaFuncAttributeMaxDynamicSharedMemorySize, 65536);
    knn_kernel<<<B_ * 128, 256, 65536>>>(pts, out);

    cudaFuncSetAttribute(point_kernel, cudaFuncAttributeMaxDynamicSharedMemorySize,
                         (int)sizeof(PSmem));
    point_kernel<<<B_ * P_ / M_, PT_, sizeof(PSmem)>>>(pts, features,
                                   w_fts0, bn_fts0, w_fts1, bn_fts1,
                                   w_x0, bn_x0, w_x1, bn_x1, w_x2, bn_x2,
                                   w_dw, w_pw, bn_sep, out);
}

// round 12
// speedup vs baseline: 1.6548x; 1.0719x over previous
#include <cuda_runtime.h>
#include <math_constants.h>

#define B_   8
#define N_   4096
#define F_   64
#define P_   1024
#define K_   16
#define CPF_ 32
#define CF_  96      // CPF + F
#define C_   128
#define DM_  2
#define KK_  256     // K*K
#define EPS_ 0.001f
#define M_   4       // points per block in point_kernel
#define PT_  256     // point_kernel threads

// Scratch for kNN indices (allocation-free rule: __device__ global)
__device__ int g_idx[B_ * P_ * K_];

// ---------------------------------------------------------------------------
// kNN: warp per query. Warp-distributed sorted top-32 (lane l = rank l).
// FROZEN numerics: dot = k-ordered FMA chain; norms = square+reduce no FMA;
// d2 = (|q|^2 - 2*dot) + |p|^2; lexicographic (d2, index) tie-break.
// Also writes the qrs passthrough (out[0 : B*P*3)).
// ---------------------------------------------------------------------------
__global__ void knn_kernel(const float* __restrict__ pts, float* __restrict__ out) {
    extern __shared__ float4 sp[];   // 4096 x (x, y, z, |p|^2) = 64 KB

    const int batch = blockIdx.x >> 7;      // 128 blocks per batch
    const int warp  = threadIdx.x >> 5;     // 8 warps = 8 queries / block
    const int lane  = threadIdx.x & 31;

    const float* bp = pts + batch * N_ * 3;
    for (int i = threadIdx.x; i < N_; i += blockDim.x) {
        float x = bp[i * 3 + 0], y = bp[i * 3 + 1], z = bp[i * 3 + 2];
        float pn = __fadd_rn(__fadd_rn(__fmul_rn(x, x), __fmul_rn(y, y)), __fmul_rn(z, z));
        sp[i] = make_float4(x, y, z, pn);
    }
    {
        int base = ((blockIdx.x & 127) << 3) * 3;
        if (threadIdx.x < 24)
            out[batch * P_ * 3 + base + threadIdx.x] = bp[base + threadIdx.x];
    }
    __syncthreads();

    const int p = ((blockIdx.x & 127) << 3) + warp;
    const float4 q = sp[p];

    float ld = CUDART_INF_F;     // this lane's list element (rank = lane)
    int   li = 0x7fffffff;
    float thr_d = CUDART_INF_F;  // broadcast copy of rank-31 entry
    int   thr_i = 0x7fffffff;
    const unsigned FULL = 0xffffffffu;

    #pragma unroll 1
    for (int r = 0; r < N_ / 32; r++) {
        int n = (r << 5) + lane;
        float4 c = sp[n];
        float dot = __fmaf_rn(q.z, c.z, __fmaf_rn(q.y, c.y, __fmul_rn(q.x, c.x)));
        float d2 = __fadd_rn(__fsub_rn(q.w, __fmul_rn(2.0f, dot)), c.w);

        bool pass = (d2 < thr_d) || (d2 == thr_d && n < thr_i);
        unsigned mask = __ballot_sync(FULL, pass);
        if (mask) {
            do {
                int src = __ffs(mask) - 1;
                mask &= mask - 1;
                float dn = __shfl_sync(FULL, d2, src);
                int   in = __shfl_sync(FULL, n, src);
                bool gt = (ld > dn) || (ld == dn && li > in);
                unsigned gb = __ballot_sync(FULL, gt);
                float pd = __shfl_up_sync(FULL, ld, 1);
                int   pi = __shfl_up_sync(FULL, li, 1);
                if (gb) {                       // else: worse than all 32, drop
                    int pos = __ffs(gb) - 1;
                    if (lane > pos)      { ld = pd; li = pi; }
                    else if (lane == pos){ ld = dn; li = in; }
                }
            } while (mask);
            thr_d = __shfl_sync(FULL, ld, 31);
            thr_i = __shfl_sync(FULL, li, 31);
        }
    }
    // dilation D=2: keep even ranks 0,2,...,30
    if (!(lane & 1))
        g_idx[(batch * P_ + p) * K_ + (lane >> 1)] = li;
}

// ---------------------------------------------------------------------------
// Fused MLP chain, M_=4 points per block, 256 threads, 5 blocks/SM.
// R11: per-point smem operands loaded via LDS.128 (float4), components
// consumed in ascending order -> identical FP accumulation, ~2x fewer
// L1 wavefronts.
// ---------------------------------------------------------------------------
__device__ __forceinline__ float elu_f(float x) {
    return x > 0.0f ? x : expm1f(x);
}

struct PSmem {
    int   idx[M_][K_];            // 256 B
    float local[M_][K_ * 3];      // 768 B  (rows 192 B, 16B-aligned)
    float nnin[M_][K_][CF_];      // 24 KB   cols [0:32)=f, [32:96)=features
    float h0[M_][K_][CPF_];       // 8 KB   (rows 128 B)
    float xa[M_][KK_];            // 4 KB   (rows 1024 B)
    float xb[M_][KK_];            // 4 KB
    float t[M_][CF_ * DM_];       // 3 KB   (rows 768 B)
};                                // ~44.3 KB -> 5 blocks/SM

__global__ __launch_bounds__(PT_, 5) void point_kernel(
    const float* __restrict__ pts,    const float* __restrict__ features,
    const float* __restrict__ w_fts0, const float* __restrict__ bn_fts0,
    const float* __restrict__ w_fts1, const float* __restrict__ bn_fts1,
    const float* __restrict__ w_x0,   const float* __restrict__ bn_x0,
    const float* __restrict__ w_x1,   const float* __restrict__ bn_x1,
    const float* __restrict__ w_x2,   const float* __restrict__ bn_x2,
    const float* __restrict__ w_dw,   const float* __restrict__ w_pw,
    const float* __restrict__ bn_sep, float* __restrict__ out)
{
    extern __shared__ char smem_raw[];
    PSmem& S = *reinterpret_cast<PSmem*>(smem_raw);

    const int tid = threadIdx.x;
    const int b   = blockIdx.x >> 8;               // 256 blocks per batch
    const int pq0 = (blockIdx.x & 255) * M_;       // first query idx in batch
    const int pg0 = blockIdx.x * M_;               // first global point idx

    if (tid < M_ * K_)
        S.idx[tid >> 4][tid & 15] = g_idx[pg0 * K_ + tid];
    __syncthreads();

    const float* bpts = pts + b * N_ * 3;
    if (tid < M_ * 48) {                     // 192 <= 256 threads: single pass
        int p = tid / 48, r = tid - p * 48;
        int k = r / 3, c = r - 3 * k;
        S.local[p][r] = bpts[S.idx[p][k] * 3 + c] - bpts[(pq0 + p) * 3 + c];
    }
    // features: float4 loads (F_=64 -> 16 float4 per neighbor row)
    const float4* bft4 = (const float4*)(features + b * N_ * F_);
    for (int e = tid; e < M_ * K_ * (F_ / 4); e += PT_) {
        int p = e >> 8, k = (e >> 4) & 15, f4 = e & 15;
        float4 v = __ldg(bft4 + S.idx[p][k] * (F_ / 4) + f4);
        *(float4*)&S.nnin[p][k][CPF_ + f4 * 4] = v;
    }
    __syncthreads();

    // stage A: h0 = bn0(elu(local @ w_fts0))   (M x 16 x 32)
    for (int e = tid; e < K_ * CPF_; e += PT_) {
        int k = e >> 5, j = e & 31;
        float w0 = __ldg(w_fts0 + 0 * CPF_ + j);
        float w1 = __ldg(w_fts0 + 1 * CPF_ + j);
        float w2 = __ldg(w_fts0 + 2 * CPF_ + j);
        float g  = __ldg(bn_fts0 + j);
        float bb = __ldg(bn_fts0 + CPF_ + j);
        float mm = __ldg(bn_fts0 + 2 * CPF_ + j);
        float vv = __ldg(bn_fts0 + 3 * CPF_ + j);
        float rs = __fdiv_rn(1.0f, __fsqrt_rn(vv + EPS_));
        #pragma unroll
        for (int p = 0; p < M_; p++) {
            float a = S.local[p][k * 3 + 0] * w0
                    + S.local[p][k * 3 + 1] * w1
                    + S.local[p][k * 3 + 2] * w2;
            S.h0[p][k][j] = (elu_f(a) - mm) * g * rs + bb;
        }
    }
    __syncthreads();

    // stage B: f = bn1(elu(h0 @ w_fts1)) -> nnin[:, :, 0:32]
    // h0 rows read as float4 blocks; j0 = j04*4+jj ascending (order preserved)
    for (int e = tid; e < K_ * CPF_; e += PT_) {
        int k = e >> 5, j = e & 31;
        float acc[M_] = {0.f, 0.f, 0.f, 0.f};
        #pragma unroll
        for (int j04 = 0; j04 < CPF_ / 4; j04++) {
            float4 h[M_];
            #pragma unroll
            for (int p = 0; p < M_; p++)
                h[p] = *(const float4*)&S.h0[p][k][j04 * 4];
            #pragma unroll
            for (int jj = 0; jj < 4; jj++) {
                float w = __ldg(w_fts1 + (j04 * 4 + jj) * CPF_ + j);
                #pragma unroll
                for (int p = 0; p < M_; p++)
                    acc[p] += ((const float*)&h[p])[jj] * w;
            }
        }
        float g  = __ldg(bn_fts1 + j);
        float bb = __ldg(bn_fts1 + CPF_ + j);
        float mm = __ldg(bn_fts1 + 2 * CPF_ + j);
        float vv = __ldg(bn_fts1 + 3 * CPF_ + j);
        float rs = __fdiv_rn(1.0f, __fsqrt_rn(vv + EPS_));
        #pragma unroll
        for (int p = 0; p < M_; p++)
            S.nnin[p][k][j] = (elu_f(acc[p]) - mm) * g * rs + bb;
    }

    // stage C: x0 = bn_x0(elu(local @ w_x0))   local read as float4 blocks
    for (int e = tid; e < KK_; e += PT_) {
        float acc[M_] = {0.f, 0.f, 0.f, 0.f};
        #pragma unroll
        for (int kq = 0; kq < 12; kq++) {
            float4 lv[M_];
            #pragma unroll
            for (int p = 0; p < M_; p++)
                lv[p] = *(const float4*)&S.local[p][kq * 4];
            #pragma unroll
            for (int ii = 0; ii < 4; ii++) {
                float w = __ldg(w_x0 + (kq * 4 + ii) * KK_ + e);
                #pragma unroll
                for (int p = 0; p < M_; p++)
                    acc[p] += ((const float*)&lv[p])[ii] * w;
            }
        }
        float g  = __ldg(bn_x0 + e);
        float bb = __ldg(bn_x0 + KK_ + e);
        float mm = __ldg(bn_x0 + 2 * KK_ + e);
        float vv = __ldg(bn_x0 + 3 * KK_ + e);
        float rs = __fdiv_rn(1.0f, __fsqrt_rn(vv + EPS_));
        #pragma unroll
        for (int p = 0; p < M_; p++)
            S.xa[p][e] = (elu_f(acc[p]) - mm) * g * rs + bb;
    }
    __syncthreads();

    // stage D: x1[c][m] = bn_x1(elu(sum_k x0[k][c] * w_x1[k][c][m]))
    for (int e = tid; e < KK_; e += PT_) {
        int c = e >> 4, m = e & 15;
        float acc[M_] = {0.f, 0.f, 0.f, 0.f};
        #pragma unroll
        for (int k = 0; k < 16; k++) {
            float w = __ldg(w_x1 + (k * 16 + c) * 16 + m);
            #pragma unroll
            for (int p = 0; p < M_; p++) acc[p] += S.xa[p][k * 16 + c] * w;
        }
        float g  = __ldg(bn_x1 + e);
        float bb = __ldg(bn_x1 + KK_ + e);
        float mm = __ldg(bn_x1 + 2 * KK_ + e);
        float vv = __ldg(bn_x1 + 3 * KK_ + e);
        float rs = __fdiv_rn(1.0f, __fsqrt_rn(vv + EPS_));
        #pragma unroll
        for (int p = 0; p < M_; p++)
            S.xb[p][e] = (elu_f(acc[p]) - mm) * g * rs + bb;
    }
    __syncthreads();

    // stage E: x2[c][m] = bn_x2(sum_k x1[k][c] * w_x2[k][c][m])  (no elu)
    for (int e = tid; e < KK_; e += PT_) {
        int c = e >> 4, m = e & 15;
        float acc[M_] = {0.f, 0.f, 0.f, 0.f};
        #pragma unroll
        for (int k = 0; k < 16; k++) {
            float w = __ldg(w_x2 + (k * 16 + c) * 16 + m);
            #pragma unroll
            for (int p = 0; p < M_; p++) acc[p] += S.xb[p][k * 16 + c] * w;
        }
        float g  = __ldg(bn_x2 + e);
        float bb = __ldg(bn_x2 + KK_ + e);
        float mm = __ldg(bn_x2 + 2 * KK_ + e);
        float vv = __ldg(bn_x2 + 3 * KK_ + e);
        float rs = __fdiv_rn(1.0f, __fsqrt_rn(vv + EPS_));
        #pragma unroll
        for (int p = 0; p < M_; p++)
            S.xa[p][e] = (acc[p] - mm) * g * rs + bb;
    }
    __syncthreads();

    // stage F+G, per-(p,c) thread; xa rows read as float4 (j ascending inside k).
    for (int e = tid; e < M_ * CF_; e += PT_) {
        int p = e / CF_, c = e - p * CF_;
        float nnj[K_];
        #pragma unroll
        for (int j = 0; j < K_; j++) nnj[j] = S.nnin[p][j][c];
        float t0 = 0.0f, t1 = 0.0f;
        #pragma unroll
        for (int k = 0; k < K_; k++) {
            float fx = 0.0f;
            #pragma unroll
            for (int j4 = 0; j4 < 4; j4++) {
                float4 xv = *(const float4*)&S.xa[p][k * 16 + j4 * 4];
                fx += xv.x * nnj[j4 * 4 + 0];
                fx += xv.y * nnj[j4 * 4 + 1];
                fx += xv.z * nnj[j4 * 4 + 2];
                fx += xv.w * nnj[j4 * 4 + 3];
            }
            float2 wd = __ldg((const float2*)w_dw + k * CF_ + c);
            t0 += fx * wd.x;
            t1 += fx * wd.y;
        }
        S.t[p][c * DM_ + 0] = t0;
        S.t[p][c * DM_ + 1] = t1;
    }
    __syncthreads();

    // stage H: out[o] = bn_sep(elu(sum_i t[i] * w_pw[i][o]))
    // t read as float4 blocks; i = i4*4+ii ascending (order preserved)
    if (tid < C_) {
        int o = tid;
        float acc[M_] = {0.f, 0.f, 0.f, 0.f};
        #pragma unroll 4
        for (int i4 = 0; i4 < (CF_ * DM_) / 4; i4++) {
            float4 tv[M_];
            #pragma unroll
            for (int p = 0; p < M_; p++)
                tv[p] = *(const float4*)&S.t[p][i4 * 4];
            #pragma unroll
            for (int ii = 0; ii < 4; ii++) {
                float w = __ldg(w_pw + (i4 * 4 + ii) * C_ + o);
                #pragma unroll
                for (int p = 0; p < M_; p++)
                    acc[p] += ((const float*)&tv[p])[ii] * w;
            }
        }
        float g  = __ldg(bn_sep + o);
        float bb = __ldg(bn_sep + C_ + o);
        float mm = __ldg(bn_sep + 2 * C_ + o);
        float vv = __ldg(bn_sep + 3 * C_ + o);
        float rs = __fdiv_rn(1.0f, __fsqrt_rn(vv + EPS_));
        #pragma unroll
        for (int p = 0; p < M_; p++)
            out[B_ * P_ * 3 + (pg0 + p) * C_ + o] = (elu_f(acc[p]) - mm) * g * rs + bb;
    }
}

// ---------------------------------------------------------------------------
extern "C" void kernel_launch(void* const* d_in, const int* in_sizes, int n_in,
                              void* d_out, int out_size) {
    const float* pts      = (const float*)d_in[0];
    const float* features = (const float*)d_in[1];
    const float* w_fts0   = (const float*)d_in[2];
    const float* bn_fts0  = (const float*)d_in[3];
    const float* w_fts1   = (const float*)d_in[4];
    const float* bn_fts1  = (const float*)d_in[5];
    const float* w_x0     = (const float*)d_in[6];
    const float* bn_x0    = (const float*)d_in[7];
    const float* w_x1     = (const float*)d_in[8];
    const float* bn_x1    = (const float*)d_in[9];
    const float* w_x2     = (const float*)d_in[10];
    const float* bn_x2    = (const float*)d_in[11];
    const float* w_dw     = (const float*)d_in[12];
    const float* w_pw     = (const float*)d_in[13];
    const float* bn_sep   = (const float*)d_in[14];
    float* out = (float*)d_out;

    cudaFuncSetAttribute(knn_kernel, cudaFuncAttributeMaxDynamicSharedMemorySize, 65536);
    knn_kernel<<<B_ * 128, 256, 65536>>>(pts, out);

    cudaFuncSetAttribute(point_kernel, cudaFuncAttributeMaxDynamicSharedMemorySize,
                         (int)sizeof(PSmem));
    point_kernel<<<B_ * P_ / M_, PT_, sizeof(PSmem)>>>(pts, features,
                                   w_fts0, bn_fts0, w_fts1, bn_fts1,
                                   w_x0, bn_x0, w_x1, bn_x1, w_x2, bn_x2,
                                   w_dw, w_pw, bn_sep, out);
}

// round 13
// speedup vs baseline: 2.0718x; 1.2520x over previous
#include <cuda_runtime.h>
#include <math_constants.h>

#define B_   8
#define N_   4096
#define F_   64
#define P_   1024
#define K_   16
#define CPF_ 32
#define CF_  96      // CPF + F
#define C_   128
#define DM_  2
#define KK_  256     // K*K
#define EPS_ 0.001f
#define M_   4       // points per block in point_kernel
#define PT_  256     // point_kernel threads

#define KNN_SMEM (65536 + 8 * 64 * 8)   // sp cache + per-warp candidate buffers

// Scratch for kNN indices (allocation-free rule: __device__ global)
__device__ int g_idx[B_ * P_ * K_];

// ---------------------------------------------------------------------------
// kNN: warp per query, batched top-32.
// FROZEN numerics: dot = k-ordered FMA chain; norms = square+reduce no FMA;
// d2 = (|q|^2 - 2*dot) + |p|^2; TOTAL ORDER = lexicographic (d2, index).
// R13: passing candidates buffered in smem; every 32, bitonic sort + top-k
// merge with the resident sorted list (lane l = rank l). Same total order as
// serial insertion -> identical result, ~2x fewer SHFL-class ops.
// ---------------------------------------------------------------------------
__device__ __forceinline__ bool lex_gt(float a, int ai, float b, int bi) {
    return (a > b) || (a == b && ai > bi);
}

// Sort 32 (sd,si) across lanes ascending-lex, then merge top-32 into (ld,li).
__device__ __forceinline__ void topk_flush(float& ld, int& li, float sd, int si,
                                           int lane) {
    const unsigned FULL = 0xffffffffu;
    // full bitonic sort of the batch (ascending lex)
    #pragma unroll
    for (int k = 2; k <= 32; k <<= 1) {
        #pragma unroll
        for (int j = k >> 1; j > 0; j >>= 1) {
            float od = __shfl_xor_sync(FULL, sd, j);
            int   oi = __shfl_xor_sync(FULL, si, j);
            bool up    = ((lane & k) == 0);
            bool lower = ((lane & j) == 0);
            bool gt = lex_gt(sd, si, od, oi);
            bool takeOther = up ? (lower ? gt : !gt) : (lower ? !gt : gt);
            if (takeOther) { sd = od; si = oi; }
        }
    }
    // elementwise lex-min of list and reversed batch -> bitonic sequence of top-32
    {
        float rd = __shfl_xor_sync(FULL, sd, 31);
        int   ri = __shfl_xor_sync(FULL, si, 31);
        if (lex_gt(ld, li, rd, ri)) { ld = rd; li = ri; }
    }
    // bitonic merge -> fully sorted ascending
    #pragma unroll
    for (int j = 16; j > 0; j >>= 1) {
        float od = __shfl_xor_sync(FULL, ld, j);
        int   oi = __shfl_xor_sync(FULL, li, j);
        bool lower = ((lane & j) == 0);
        bool gt = lex_gt(ld, li, od, oi);
        bool takeOther = lower ? gt : !gt;
        if (takeOther) { ld = od; li = oi; }
    }
}

__global__ void knn_kernel(const float* __restrict__ pts, float* __restrict__ out) {
    extern __shared__ char smem_raw[];
    float4* sp   = (float4*)smem_raw;                       // 4096 x 16B = 64 KB
    float*  bufd = (float*)(smem_raw + 65536);              // 8 warps x 64
    int*    bufi = (int*)  (smem_raw + 65536 + 8 * 64 * 4); // 8 warps x 64

    const int batch = blockIdx.x >> 7;      // 128 blocks per batch
    const int warp  = threadIdx.x >> 5;     // 8 warps = 8 queries / block
    const int lane  = threadIdx.x & 31;

    const float* bp = pts + batch * N_ * 3;
    for (int i = threadIdx.x; i < N_; i += blockDim.x) {
        float x = bp[i * 3 + 0], y = bp[i * 3 + 1], z = bp[i * 3 + 2];
        float pn = __fadd_rn(__fadd_rn(__fmul_rn(x, x), __fmul_rn(y, y)), __fmul_rn(z, z));
        sp[i] = make_float4(x, y, z, pn);
    }
    {
        int base = ((blockIdx.x & 127) << 3) * 3;
        if (threadIdx.x < 24)
            out[batch * P_ * 3 + base + threadIdx.x] = bp[base + threadIdx.x];
    }
    __syncthreads();

    const int p = ((blockIdx.x & 127) << 3) + warp;
    const float4 q = sp[p];

    float* wbd = bufd + warp * 64;
    int*   wbi = bufi + warp * 64;

    float ld = CUDART_INF_F;     // resident sorted list: lane l = rank l
    int   li = 0x7fffffff;
    float thr_d = CUDART_INF_F;  // broadcast rank-31 (refreshed per flush)
    int   thr_i = 0x7fffffff;
    int   bufcnt = 0;
    const unsigned FULL = 0xffffffffu;

    #pragma unroll 1
    for (int r = 0; r < N_ / 32; r++) {
        int n = (r << 5) + lane;
        float4 c = sp[n];
        float dot = __fmaf_rn(q.z, c.z, __fmaf_rn(q.y, c.y, __fmul_rn(q.x, c.x)));
        float d2 = __fadd_rn(__fsub_rn(q.w, __fmul_rn(2.0f, dot)), c.w);

        bool pass = (d2 < thr_d) || (d2 == thr_d && n < thr_i);
        unsigned mask = __ballot_sync(FULL, pass);
        if (mask) {
            if (pass) {
                int pos = bufcnt + __popc(mask & ((1u << lane) - 1u));
                wbd[pos] = d2;
                wbi[pos] = n;
            }
            bufcnt += __popc(mask);
            if (bufcnt >= 32) {
                bufcnt -= 32;
                __syncwarp(FULL);                    // STS -> LDS ordering
                float sd = wbd[bufcnt + lane];
                int   si = wbi[bufcnt + lane];
                __syncwarp(FULL);                    // LDS before later STS (WAR)
                topk_flush(ld, li, sd, si, lane);
                thr_d = __shfl_sync(FULL, ld, 31);
                thr_i = __shfl_sync(FULL, li, 31);
            }
        }
    }
    if (bufcnt > 0) {                                // final partial flush (pad inf)
        __syncwarp(FULL);
        float sd = (lane < bufcnt) ? wbd[lane] : CUDART_INF_F;
        int   si = (lane < bufcnt) ? wbi[lane] : 0x7fffffff;
        topk_flush(ld, li, sd, si, lane);
    }
    // dilation D=2: keep even ranks 0,2,...,30
    if (!(lane & 1))
        g_idx[(batch * P_ + p) * K_ + (lane >> 1)] = li;
}

// ---------------------------------------------------------------------------
// Fused MLP chain, M_=4 points per block, 256 threads, 5 blocks/SM.
// (unchanged from R12 — passed at 95.9us, rel_err 2.287413e-07)
// ---------------------------------------------------------------------------
__device__ __forceinline__ float elu_f(float x) {
    return x > 0.0f ? x : expm1f(x);
}

struct PSmem {
    int   idx[M_][K_];            // 256 B
    float local[M_][K_ * 3];      // 768 B  (rows 192 B, 16B-aligned)
    float nnin[M_][K_][CF_];      // 24 KB   cols [0:32)=f, [32:96)=features
    float h0[M_][K_][CPF_];       // 8 KB   (rows 128 B)
    float xa[M_][KK_];            // 4 KB   (rows 1024 B)
    float xb[M_][KK_];            // 4 KB
    float t[M_][CF_ * DM_];       // 3 KB   (rows 768 B)
};                                // ~44.3 KB -> 5 blocks/SM

__global__ __launch_bounds__(PT_, 5) void point_kernel(
    const float* __restrict__ pts,    const float* __restrict__ features,
    const float* __restrict__ w_fts0, const float* __restrict__ bn_fts0,
    const float* __restrict__ w_fts1, const float* __restrict__ bn_fts1,
    const float* __restrict__ w_x0,   const float* __restrict__ bn_x0,
    const float* __restrict__ w_x1,   const float* __restrict__ bn_x1,
    const float* __restrict__ w_x2,   const float* __restrict__ bn_x2,
    const float* __restrict__ w_dw,   const float* __restrict__ w_pw,
    const float* __restrict__ bn_sep, float* __restrict__ out)
{
    extern __shared__ char smem_raw[];
    PSmem& S = *reinterpret_cast<PSmem*>(smem_raw);

    const int tid = threadIdx.x;
    const int b   = blockIdx.x >> 8;               // 256 blocks per batch
    const int pq0 = (blockIdx.x & 255) * M_;       // first query idx in batch
    const int pg0 = blockIdx.x * M_;               // first global point idx

    if (tid < M_ * K_)
        S.idx[tid >> 4][tid & 15] = g_idx[pg0 * K_ + tid];
    __syncthreads();

    const float* bpts = pts + b * N_ * 3;
    if (tid < M_ * 48) {                     // 192 <= 256 threads: single pass
        int p = tid / 48, r = tid - p * 48;
        int k = r / 3, c = r - 3 * k;
        S.local[p][r] = bpts[S.idx[p][k] * 3 + c] - bpts[(pq0 + p) * 3 + c];
    }
    // features: float4 loads (F_=64 -> 16 float4 per neighbor row)
    const float4* bft4 = (const float4*)(features + b * N_ * F_);
    for (int e = tid; e < M_ * K_ * (F_ / 4); e += PT_) {
        int p = e >> 8, k = (e >> 4) & 15, f4 = e & 15;
        float4 v = __ldg(bft4 + S.idx[p][k] * (F_ / 4) + f4);
        *(float4*)&S.nnin[p][k][CPF_ + f4 * 4] = v;
    }
    __syncthreads();

    // stage A: h0 = bn0(elu(local @ w_fts0))   (M x 16 x 32)
    for (int e = tid; e < K_ * CPF_; e += PT_) {
        int k = e >> 5, j = e & 31;
        float w0 = __ldg(w_fts0 + 0 * CPF_ + j);
        float w1 = __ldg(w_fts0 + 1 * CPF_ + j);
        float w2 = __ldg(w_fts0 + 2 * CPF_ + j);
        float g  = __ldg(bn_fts0 + j);
        float bb = __ldg(bn_fts0 + CPF_ + j);
        float mm = __ldg(bn_fts0 + 2 * CPF_ + j);
        float vv = __ldg(bn_fts0 + 3 * CPF_ + j);
        float rs = __fdiv_rn(1.0f, __fsqrt_rn(vv + EPS_));
        #pragma unroll
        for (int p = 0; p < M_; p++) {
            float a = S.local[p][k * 3 + 0] * w0
                    + S.local[p][k * 3 + 1] * w1
                    + S.local[p][k * 3 + 2] * w2;
            S.h0[p][k][j] = (elu_f(a) - mm) * g * rs + bb;
        }
    }
    __syncthreads();

    // stage B: f = bn1(elu(h0 @ w_fts1)) -> nnin[:, :, 0:32]
    for (int e = tid; e < K_ * CPF_; e += PT_) {
        int k = e >> 5, j = e & 31;
        float acc[M_] = {0.f, 0.f, 0.f, 0.f};
        #pragma unroll
        for (int j04 = 0; j04 < CPF_ / 4; j04++) {
            float4 h[M_];
            #pragma unroll
            for (int p = 0; p < M_; p++)
                h[p] = *(const float4*)&S.h0[p][k][j04 * 4];
            #pragma unroll
            for (int jj = 0; jj < 4; jj++) {
                float w = __ldg(w_fts1 + (j04 * 4 + jj) * CPF_ + j);
                #pragma unroll
                for (int p = 0; p < M_; p++)
                    acc[p] += ((const float*)&h[p])[jj] * w;
            }
        }
        float g  = __ldg(bn_fts1 + j);
        float bb = __ldg(bn_fts1 + CPF_ + j);
        float mm = __ldg(bn_fts1 + 2 * CPF_ + j);
        float vv = __ldg(bn_fts1 + 3 * CPF_ + j);
        float rs = __fdiv_rn(1.0f, __fsqrt_rn(vv + EPS_));
        #pragma unroll
        for (int p = 0; p < M_; p++)
            S.nnin[p][k][j] = (elu_f(acc[p]) - mm) * g * rs + bb;
    }

    // stage C: x0 = bn_x0(elu(local @ w_x0))   local read as float4 blocks
    for (int e = tid; e < KK_; e += PT_) {
        float acc[M_] = {0.f, 0.f, 0.f, 0.f};
        #pragma unroll
        for (int kq = 0; kq < 12; kq++) {
            float4 lv[M_];
            #pragma unroll
            for (int p = 0; p < M_; p++)
                lv[p] = *(const float4*)&S.local[p][kq * 4];
            #pragma unroll
            for (int ii = 0; ii < 4; ii++) {
                float w = __ldg(w_x0 + (kq * 4 + ii) * KK_ + e);
                #pragma unroll
                for (int p = 0; p < M_; p++)
                    acc[p] += ((const float*)&lv[p])[ii] * w;
            }
        }
        float g  = __ldg(bn_x0 + e);
        float bb = __ldg(bn_x0 + KK_ + e);
        float mm = __ldg(bn_x0 + 2 * KK_ + e);
        float vv = __ldg(bn_x0 + 3 * KK_ + e);
        float rs = __fdiv_rn(1.0f, __fsqrt_rn(vv + EPS_));
        #pragma unroll
        for (int p = 0; p < M_; p++)
            S.xa[p][e] = (elu_f(acc[p]) - mm) * g * rs + bb;
    }
    __syncthreads();

    // stage D: x1[c][m] = bn_x1(elu(sum_k x0[k][c] * w_x1[k][c][m]))
    for (int e = tid; e < KK_; e += PT_) {
        int c = e >> 4, m = e & 15;
        float acc[M_] = {0.f, 0.f, 0.f, 0.f};
        #pragma unroll
        for (int k = 0; k < 16; k++) {
            float w = __ldg(w_x1 + (k * 16 + c) * 16 + m);
            #pragma unroll
            for (int p = 0; p < M_; p++) acc[p] += S.xa[p][k * 16 + c] * w;
        }
        float g  = __ldg(bn_x1 + e);
        float bb = __ldg(bn_x1 + KK_ + e);
        float mm = __ldg(bn_x1 + 2 * KK_ + e);
        float vv = __ldg(bn_x1 + 3 * KK_ + e);
        float rs = __fdiv_rn(1.0f, __fsqrt_rn(vv + EPS_));
        #pragma unroll
        for (int p = 0; p < M_; p++)
            S.xb[p][e] = (elu_f(acc[p]) - mm) * g * rs + bb;
    }
    __syncthreads();

    // stage E: x2[c][m] = bn_x2(sum_k x1[k][c] * w_x2[k][c][m])  (no elu)
    for (int e = tid; e < KK_; e += PT_) {
        int c = e >> 4, m = e & 15;
        float acc[M_] = {0.f, 0.f, 0.f, 0.f};
        #pragma unroll
        for (int k = 0; k < 16; k++) {
            float w = __ldg(w_x2 + (k * 16 + c) * 16 + m);
            #pragma unroll
            for (int p = 0; p < M_; p++) acc[p] += S.xb[p][k * 16 + c] * w;
        }
        float g  = __ldg(bn_x2 + e);
        float bb = __ldg(bn_x2 + KK_ + e);
        float mm = __ldg(bn_x2 + 2 * KK_ + e);
        float vv = __ldg(bn_x2 + 3 * KK_ + e);
        float rs = __fdiv_rn(1.0f, __fsqrt_rn(vv + EPS_));
        #pragma unroll
        for (int p = 0; p < M_; p++)
            S.xa[p][e] = (acc[p] - mm) * g * rs + bb;
    }
    __syncthreads();

    // stage F+G, per-(p,c) thread; xa rows read as float4 (j ascending inside k).
    for (int e = tid; e < M_ * CF_; e += PT_) {
        int p = e / CF_, c = e - p * CF_;
        float nnj[K_];
        #pragma unroll
        for (int j = 0; j < K_; j++) nnj[j] = S.nnin[p][j][c];
        float t0 = 0.0f, t1 = 0.0f;
        #pragma unroll
        for (int k = 0; k < K_; k++) {
            float fx = 0.0f;
            #pragma unroll
            for (int j4 = 0; j4 < 4; j4++) {
                float4 xv = *(const float4*)&S.xa[p][k * 16 + j4 * 4];
                fx += xv.x * nnj[j4 * 4 + 0];
                fx += xv.y * nnj[j4 * 4 + 1];
                fx += xv.z * nnj[j4 * 4 + 2];
                fx += xv.w * nnj[j4 * 4 + 3];
            }
            float2 wd = __ldg((const float2*)w_dw + k * CF_ + c);
            t0 += fx * wd.x;
            t1 += fx * wd.y;
        }
        S.t[p][c * DM_ + 0] = t0;
        S.t[p][c * DM_ + 1] = t1;
    }
    __syncthreads();

    // stage H: out[o] = bn_sep(elu(sum_i t[i] * w_pw[i][o]))
    if (tid < C_) {
        int o = tid;
        float acc[M_] = {0.f, 0.f, 0.f, 0.f};
        #pragma unroll 4
        for (int i4 = 0; i4 < (CF_ * DM_) / 4; i4++) {
            float4 tv[M_];
            #pragma unroll
            for (int p = 0; p < M_; p++)
                tv[p] = *(const float4*)&S.t[p][i4 * 4];
            #pragma unroll
            for (int ii = 0; ii < 4; ii++) {
                float w = __ldg(w_pw + (i4 * 4 + ii) * C_ + o);
                #pragma unroll
                for (int p = 0; p < M_; p++)
                    acc[p] += ((const float*)&tv[p])[ii] * w;
            }
        }
        float g  = __ldg(bn_sep + o);
        float bb = __ldg(bn_sep + C_ + o);
        float mm = __ldg(bn_sep + 2 * C_ + o);
        float vv = __ldg(bn_sep + 3 * C_ + o);
        float rs = __fdiv_rn(1.0f, __fsqrt_rn(vv + EPS_));
        #pragma unroll
        for (int p = 0; p < M_; p++)
            out[B_ * P_ * 3 + (pg0 + p) * C_ + o] = (elu_f(acc[p]) - mm) * g * rs + bb;
    }
}

// ---------------------------------------------------------------------------
extern "C" void kernel_launch(void* const* d_in, const int* in_sizes, int n_in,
                              void* d_out, int out_size) {
    const float* pts      = (const float*)d_in[0];
    const float* features = (const float*)d_in[1];
    const float* w_fts0   = (const float*)d_in[2];
    const float* bn_fts0  = (const float*)d_in[3];
    const float* w_fts1   = (const float*)d_in[4];
    const float* bn_fts1  = (const float*)d_in[5];
    const float* w_x0     = (const float*)d_in[6];
    const float* bn_x0    = (const float*)d_in[7];
    const float* w_x1     = (const float*)d_in[8];
    const float* bn_x1    = (const float*)d_in[9];
    const float* w_x2     = (const float*)d_in[10];
    const float* bn_x2    = (const float*)d_in[11];
    const float* w_dw     = (const float*)d_in[12];
    const float* w_pw     = (const float*)d_in[13];
    const float* bn_sep   = (const float*)d_in[14];
    float* out = (float*)d_out;

    cudaFuncSetAttribute(knn_kernel, cudaFuncAttributeMaxDynamicSharedMemorySize, KNN_SMEM);
    knn_kernel<<<B_ * 128, 256, KNN_SMEM>>>(pts, out);

    cudaFuncSetAttribute(point_kernel, cudaFuncAttributeMaxDynamicSharedMemorySize,
                         (int)sizeof(PSmem));
    point_kernel<<<B_ * P_ / M_, PT_, sizeof(PSmem)>>>(pts, features,
                                   w_fts0, bn_fts0, w_fts1, bn_fts1,
                                   w_x0, bn_x0, w_x1, bn_x1, w_x2, bn_x2,
                                   w_dw, w_pw, bn_sep, out);
}